// round 5
// baseline (speedup 1.0000x reference)
#include <cuda_runtime.h>
#include <cuda_bf16.h>

// BCE-with-logits mean loss, single fused kernel.
//   loss = mean softplus( target==0 ? x : -x )
// Identity used: softplus((t==0)?x:-x) = max(x,0) - t*x + log(1+exp(-|x|))
//   -> the log term is target-independent; only a predicated subtract depends on t.
// Log-pairing: sum of log(1+e_i) over 4 lanes = log(prod(1+e_i)), prod in (1,16].
//
// Memory-bound: 512 MB streaming read. __ldcs (evict-first) + 2x unrolled
// grid-stride loop for deeper LDG batching. Init of the output is folded in
// via a last-block pattern on __device__ scratch (no separate init launch).

#define THREADS 256
#define BLOCKS  (148 * 16)

__device__ float        g_partial = 0.0f;
__device__ unsigned int g_count   = 0u;

__device__ __forceinline__ float group4(float4 x, int4 t) {
    // max(x,0) - t*x terms
    float m = fmaxf(x.x, 0.0f) + fmaxf(x.y, 0.0f)
            + fmaxf(x.z, 0.0f) + fmaxf(x.w, 0.0f);
    if (t.x) m -= x.x;
    if (t.y) m -= x.y;
    if (t.z) m -= x.z;
    if (t.w) m -= x.w;

    // log(1+exp(-|x|)) terms, paired into one log
    float e0 = __expf(-fabsf(x.x));
    float e1 = __expf(-fabsf(x.y));
    float e2 = __expf(-fabsf(x.z));
    float e3 = __expf(-fabsf(x.w));
    float p = (1.0f + e0) * (1.0f + e1) * (1.0f + e2) * (1.0f + e3);
    return m + __logf(p);
}

__global__ __launch_bounds__(THREADS) void bce_reduce_kernel(
    const float4* __restrict__ x4,
    const int4*   __restrict__ t4,
    float* __restrict__ out,
    long long n4,
    float inv_n)
{
    const long long stride = (long long)gridDim.x * blockDim.x;
    long long i = (long long)blockIdx.x * blockDim.x + threadIdx.x;

    float acc = 0.0f;

    // 2x unrolled main loop: 4 independent 16B streaming loads in flight
    for (; i + stride < n4; i += 2 * stride) {
        float4 xa = __ldcs(&x4[i]);
        int4   ta = __ldcs(&t4[i]);
        float4 xb = __ldcs(&x4[i + stride]);
        int4   tb = __ldcs(&t4[i + stride]);
        acc += group4(xa, ta);
        acc += group4(xb, tb);
    }
    if (i < n4) {
        float4 xa = __ldcs(&x4[i]);
        int4   ta = __ldcs(&t4[i]);
        acc += group4(xa, ta);
    }

    // warp reduce
    #pragma unroll
    for (int off = 16; off > 0; off >>= 1)
        acc += __shfl_xor_sync(0xFFFFFFFFu, acc, off);

    // cross-warp reduce
    __shared__ float warp_sums[THREADS / 32];
    int lane = threadIdx.x & 31;
    int warp = threadIdx.x >> 5;
    if (lane == 0) warp_sums[warp] = acc;
    __syncthreads();

    if (warp == 0) {
        float v = (lane < THREADS / 32) ? warp_sums[lane] : 0.0f;
        #pragma unroll
        for (int off = (THREADS / 64); off > 0; off >>= 1)
            v += __shfl_xor_sync(0xFFFFFFFFu, v, off);

        if (lane == 0) {
            atomicAdd(&g_partial, v);
            __threadfence();
            unsigned int ticket = atomicInc(&g_count, gridDim.x - 1);
            if (ticket == gridDim.x - 1) {
                // last block: consume + reset scratch for the next graph replay
                float total = atomicExch(&g_partial, 0.0f);
                *out = total * inv_n;
            }
        }
    }
}

extern "C" void kernel_launch(void* const* d_in, const int* in_sizes, int n_in,
                              void* d_out, int out_size) {
    const float* x = (const float*)d_in[0];   // logits, float32
    const int*   t = (const int*)d_in[1];     // targets, int32 in {0,1}
    float* out = (float*)d_out;

    long long n  = (long long)in_sizes[0];    // 8192*8192, divisible by 4
    long long n4 = n / 4;
    float inv_n = 1.0f / (float)n;

    bce_reduce_kernel<<<BLOCKS, THREADS>>>(
        (const float4*)x, (const int4*)t, out, n4, inv_n);
}

// round 8
// speedup vs baseline: 1.0306x; 1.0306x over previous
#include <cuda_runtime.h>
#include <cuda_bf16.h>

// BCE-with-logits mean loss, single fused kernel (R4 loop body + folded init).
//   loss = mean softplus( target==0 ? x : -x ),
//   softplus(y) = max(y,0) + log(1+exp(-|y|)).
// Log-pairing: sum of log(1+e_i) over 4 lanes = log(prod(1+e_i)), prod in (1,16].
//
// At the LTS ceiling (~6300 B/cyc): 512 MB streaming read -> ~78 us floor.
// Single wave: 148 SMs x 8 CTAs x 256 threads, 32 regs (launch_bounds-pinned).
// Output init folded in via last-block pattern on __device__ scratch.

#define THREADS 256
#define BLOCKS  (148 * 8)

__device__ float        g_partial = 0.0f;
__device__ unsigned int g_count   = 0u;

__global__ __launch_bounds__(THREADS, 8) void bce_reduce_kernel(
    const float4* __restrict__ x4,
    const int4*   __restrict__ t4,
    float* __restrict__ out,
    long long n4,
    float inv_n)
{
    const long long stride = (long long)gridDim.x * blockDim.x;
    long long i = (long long)blockIdx.x * blockDim.x + threadIdx.x;

    float acc = 0.0f;

    for (; i < n4; i += stride) {
        float4 x = x4[i];
        int4   t = t4[i];

        // y = (t==0) ? x : -x
        float y0 = (t.x == 0) ? x.x : -x.x;
        float y1 = (t.y == 0) ? x.y : -x.y;
        float y2 = (t.z == 0) ? x.z : -x.z;
        float y3 = (t.w == 0) ? x.w : -x.w;

        acc += fmaxf(y0, 0.0f) + fmaxf(y1, 0.0f)
             + fmaxf(y2, 0.0f) + fmaxf(y3, 0.0f);

        float e0 = __expf(-fabsf(y0));
        float e1 = __expf(-fabsf(y1));
        float e2 = __expf(-fabsf(y2));
        float e3 = __expf(-fabsf(y3));

        float p = (1.0f + e0) * (1.0f + e1) * (1.0f + e2) * (1.0f + e3);
        acc += __logf(p);
    }

    // warp reduce
    #pragma unroll
    for (int off = 16; off > 0; off >>= 1)
        acc += __shfl_xor_sync(0xFFFFFFFFu, acc, off);

    // cross-warp reduce
    __shared__ float warp_sums[THREADS / 32];
    int lane = threadIdx.x & 31;
    int warp = threadIdx.x >> 5;
    if (lane == 0) warp_sums[warp] = acc;
    __syncthreads();

    if (warp == 0) {
        float v = (lane < THREADS / 32) ? warp_sums[lane] : 0.0f;
        #pragma unroll
        for (int off = (THREADS / 64); off > 0; off >>= 1)
            v += __shfl_xor_sync(0xFFFFFFFFu, v, off);

        if (lane == 0) {
            atomicAdd(&g_partial, v);
            __threadfence();
            unsigned int ticket = atomicInc(&g_count, gridDim.x - 1);
            if (ticket == gridDim.x - 1) {
                // last block: consume + reset scratch for next graph replay
                float total = atomicExch(&g_partial, 0.0f);
                *out = total * inv_n;
            }
        }
    }
}

extern "C" void kernel_launch(void* const* d_in, const int* in_sizes, int n_in,
                              void* d_out, int out_size) {
    const float* x = (const float*)d_in[0];   // logits, float32
    const int*   t = (const int*)d_in[1];     // targets, int32 in {0,1}
    float* out = (float*)d_out;

    long long n  = (long long)in_sizes[0];    // 8192*8192, divisible by 4
    long long n4 = n / 4;
    float inv_n = 1.0f / (float)n;

    bce_reduce_kernel<<<BLOCKS, THREADS>>>(
        (const float4*)x, (const int4*)t, out, n4, inv_n);
}

// round 9
// speedup vs baseline: 1.0462x; 1.0151x over previous
#include <cuda_runtime.h>
#include <cuda_bf16.h>

// BCE-with-logits mean loss, single fused kernel (R4 loop body + folded init).
//   loss = mean softplus( target==0 ? x : -x ),
//   softplus(y) = max(y,0) + log(1+exp(-|y|)).
// Log-pairing: sum of log(1+e_i) over 4 lanes = log(prod(1+e_i)), prod in (1,16].
//
// At the LTS ceiling (~6300 B/cyc): 512 MB streaming read -> ~78 us floor.
// Single wave: 148 SMs x 8 CTAs x 256 threads, 32 regs (launch_bounds-pinned).
// Output init folded in via last-block pattern on __device__ scratch.

#define THREADS 256
#define BLOCKS  (148 * 8)

__device__ float        g_partial = 0.0f;
__device__ unsigned int g_count   = 0u;

__global__ __launch_bounds__(THREADS, 8) void bce_reduce_kernel(
    const float4* __restrict__ x4,
    const int4*   __restrict__ t4,
    float* __restrict__ out,
    long long n4,
    float inv_n)
{
    const long long stride = (long long)gridDim.x * blockDim.x;
    long long i = (long long)blockIdx.x * blockDim.x + threadIdx.x;

    float acc = 0.0f;

    for (; i < n4; i += stride) {
        float4 x = x4[i];
        int4   t = t4[i];

        // y = (t==0) ? x : -x
        float y0 = (t.x == 0) ? x.x : -x.x;
        float y1 = (t.y == 0) ? x.y : -x.y;
        float y2 = (t.z == 0) ? x.z : -x.z;
        float y3 = (t.w == 0) ? x.w : -x.w;

        acc += fmaxf(y0, 0.0f) + fmaxf(y1, 0.0f)
             + fmaxf(y2, 0.0f) + fmaxf(y3, 0.0f);

        float e0 = __expf(-fabsf(y0));
        float e1 = __expf(-fabsf(y1));
        float e2 = __expf(-fabsf(y2));
        float e3 = __expf(-fabsf(y3));

        float p = (1.0f + e0) * (1.0f + e1) * (1.0f + e2) * (1.0f + e3);
        acc += __logf(p);
    }

    // warp reduce
    #pragma unroll
    for (int off = 16; off > 0; off >>= 1)
        acc += __shfl_xor_sync(0xFFFFFFFFu, acc, off);

    // cross-warp reduce
    __shared__ float warp_sums[THREADS / 32];
    int lane = threadIdx.x & 31;
    int warp = threadIdx.x >> 5;
    if (lane == 0) warp_sums[warp] = acc;
    __syncthreads();

    if (warp == 0) {
        float v = (lane < THREADS / 32) ? warp_sums[lane] : 0.0f;
        #pragma unroll
        for (int off = (THREADS / 64); off > 0; off >>= 1)
            v += __shfl_xor_sync(0xFFFFFFFFu, v, off);

        if (lane == 0) {
            atomicAdd(&g_partial, v);
            __threadfence();
            unsigned int ticket = atomicInc(&g_count, gridDim.x - 1);
            if (ticket == gridDim.x - 1) {
                // last block: consume + reset scratch for next graph replay
                float total = atomicExch(&g_partial, 0.0f);
                *out = total * inv_n;
            }
        }
    }
}

extern "C" void kernel_launch(void* const* d_in, const int* in_sizes, int n_in,
                              void* d_out, int out_size) {
    const float* x = (const float*)d_in[0];   // logits, float32
    const int*   t = (const int*)d_in[1];     // targets, int32 in {0,1}
    float* out = (float*)d_out;

    long long n  = (long long)in_sizes[0];    // 8192*8192, divisible by 4
    long long n4 = n / 4;
    float inv_n = 1.0f / (float)n;

    bce_reduce_kernel<<<BLOCKS, THREADS>>>(
        (const float4*)x, (const int4*)t, out, n4, inv_n);
}